// round 2
// baseline (speedup 1.0000x reference)
#include <cuda_runtime.h>
#include <math.h>

// Problem constants
#define Bq 128
#define Uq 256
#define Dq 256
#define NG 1280   // 5*U

// ---------------- scratch (static device globals; no allocation) -------------
__device__ float g_gsum[Bq * NG];                    // pre-activation gates (B,5U)
__device__ float g_c  [Bq * Uq];
__device__ float g_fre[Bq * Uq];
__device__ float g_ste[Bq * Uq];
__device__ float g_cos[Bq * Uq];
__device__ float g_sin[Bq * Uq];
__device__ float g_AT [(size_t)Bq * Uq * Uq];        // A transposed: [b][k][u], 33.5 MB

__device__ __forceinline__ float hsig(float v) {
    return fminf(fmaxf(0.2f * v + 0.5f, 0.0f), 1.0f);
}

// ============================================================================
// Kernel 1: g_gsum = x @ kernel + z_prev @ recur_k + bias   (128 x 1280)
// 64x64 tiles, 256 threads, 4x4 per-thread tile.
// ============================================================================
__global__ __launch_bounds__(256) void k_gates_gemm(
    const float* __restrict__ x, const float* __restrict__ z_prev,
    const float* __restrict__ kern, const float* __restrict__ recur,
    const float* __restrict__ bias)
{
    __shared__ float sX[16][68];   // LHS tile transposed: [u][b]
    __shared__ float sW[16][64];

    const int tid = threadIdx.x;
    const int j0  = blockIdx.x * 64;
    const int b0  = blockIdx.y * 64;
    const int rg  = tid >> 4;      // 16 row groups * 4 rows
    const int cg  = tid & 15;      // 16 col groups * 4 cols

    float acc[4][4];
#pragma unroll
    for (int i = 0; i < 4; i++)
#pragma unroll
        for (int j = 0; j < 4; j++) acc[i][j] = 0.f;

#pragma unroll
    for (int pass = 0; pass < 2; pass++) {
        const float* L = pass ? z_prev : x;       // (128, 256)
        const float* W = pass ? recur  : kern;    // (256, 1280)
        for (int d0 = 0; d0 < 256; d0 += 16) {
            // load LHS 64x16 tile (transposed into smem): 256 float4 loads
            {
                const int lb = tid >> 2;
                const int lu = (tid & 3) * 4;
                float4 v = *(const float4*)&L[(b0 + lb) * 256 + d0 + lu];
                sX[lu + 0][lb] = v.x; sX[lu + 1][lb] = v.y;
                sX[lu + 2][lb] = v.z; sX[lu + 3][lb] = v.w;
            }
            // load W 16x64 tile
            {
                const int wu = tid >> 4;
                const int wc = (tid & 15) * 4;
                *(float4*)&sW[wu][wc] = *(const float4*)&W[(d0 + wu) * NG + j0 + wc];
            }
            __syncthreads();
#pragma unroll
            for (int kk = 0; kk < 16; kk++) {
                float a[4], bb[4];
#pragma unroll
                for (int i = 0; i < 4; i++) a[i] = sX[kk][rg * 4 + i];
#pragma unroll
                for (int j = 0; j < 4; j++) bb[j] = sW[kk][cg * 4 + j];
#pragma unroll
                for (int i = 0; i < 4; i++)
#pragma unroll
                    for (int j = 0; j < 4; j++) acc[i][j] += a[i] * bb[j];
            }
            __syncthreads();
        }
    }

#pragma unroll
    for (int i = 0; i < 4; i++) {
        const int b = b0 + rg * 4 + i;
#pragma unroll
        for (int j = 0; j < 4; j++) {
            const int jj = j0 + cg * 4 + j;
            g_gsum[b * NG + jj] = acc[i][j] + bias[jj];
        }
    }
}

// ============================================================================
// Kernel 2: elementwise gates + omega output + cos/sin(theta)
// ============================================================================
__global__ __launch_bounds__(256) void k_gates_ew(
    const float* __restrict__ omg_prev, const float* __restrict__ t,
    float* __restrict__ out_omg)
{
    const int idx = blockIdx.x * blockDim.x + threadIdx.x;   // B*U = 32768
    const int b = idx >> 8;            // / 256
    const int u = idx & 255;
    const float* g = &g_gsum[b * NG];

    const float i_g = hsig(g[u]);
    const float fre = hsig(g[Uq + u]);
    const float ste = hsig(g[2 * Uq + u]);
    const float gg  = tanhf(g[3 * Uq + u]);
    const float omg = g[4 * Uq + u];

    g_c[idx]   = i_g * gg;
    g_fre[idx] = fre;
    g_ste[idx] = ste;

    const float th = omg_prev[idx] * t[b];
    g_cos[idx] = cosf(th);
    g_sin[idx] = sinf(th);

    out_omg[idx] = omg;
}

// ============================================================================
// Kernel 3: Re/Im update + A = sqrt(Re^2+Im^2), A written transposed [b][k][u]
// Block handles one b and a 64(i) x 64(j) tile; smem tile for the transpose.
// ============================================================================
__global__ __launch_bounds__(256) void k_reim(
    const float* __restrict__ Re_prev, const float* __restrict__ Im_prev,
    float* __restrict__ Im_out, float* __restrict__ Re_out)
{
    __shared__ float sA[64][65];
    const int b  = blockIdx.z;
    const int i0 = blockIdx.y * 64;
    const int j0 = blockIdx.x * 64;
    const int tj = threadIdx.x & 63;    // j within tile
    const int ti = threadIdx.x >> 6;    // 0..3

    const float fre_j = g_fre[b * Uq + j0 + tj];
    const float cosj  = g_cos[b * Uq + j0 + tj];
    const float sinj  = g_sin[b * Uq + j0 + tj];

#pragma unroll
    for (int r = 0; r < 16; r++) {
        const int i = ti + r * 4;                 // 0..63
        const float ste_i = g_ste[b * Uq + i0 + i];
        const float ci    = g_c  [b * Uq + i0 + i];
        const size_t idx = ((size_t)b * Uq + (i0 + i)) * Uq + j0 + tj;
        const float f  = ste_i * fre_j;
        const float re = f * Re_prev[idx] + ci * cosj;
        const float im = f * Im_prev[idx] + ci * sinj;
        Re_out[idx] = re;
        Im_out[idx] = im;
        sA[i][tj] = sqrtf(re * re + im * im);
    }
    __syncthreads();
    // A_T[b][j][i] = A[b][i][j]  (coalesced over i)
#pragma unroll
    for (int r = 0; r < 16; r++) {
        const int j = ti + r * 4;
        g_AT[((size_t)b * Uq + (j0 + j)) * Uq + i0 + tj] = sA[tj][j];
    }
}

// ============================================================================
// Kernel 4: per-k fused GEMMs + epilogue + k-reduction into z.
//   acc_o = A_k @ U_o[k] + x @ W_o[k] + z_prev @ V_o[k]
//   acc_z = A_k @ W_z[k]
//   z[b,v] += hsig(acc_o + b_o[k,v]) * tanh(acc_z + b_z[k,v])
// Block = (k, v-tile of 64). 128x64 output tile, 256 threads, 8x4 per thread.
// ============================================================================
__global__ __launch_bounds__(256, 2) void k_freq(
    const float* __restrict__ x_in, const float* __restrict__ z_prev,
    const float* __restrict__ freq_k, const float* __restrict__ freq_k_input,
    const float* __restrict__ freq_bias,
    float* __restrict__ z_out)
{
    __shared__ float sA [16][132];
    __shared__ float sB1[16][64];
    __shared__ float sB2[16][64];

    const int tid = threadIdx.x;
    const int k   = blockIdx.x;
    const int v0  = blockIdx.y * 64;
    const int rg  = tid >> 4;    // 16 row groups * 8 rows
    const int cg  = tid & 15;    // 16 col groups * 4 cols

    float acc_o[8][4];
    float acc_z[8][4];
#pragma unroll
    for (int i = 0; i < 8; i++)
#pragma unroll
        for (int j = 0; j < 4; j++) { acc_o[i][j] = 0.f; acc_z[i][j] = 0.f; }

    const float* Uo = freq_k + (size_t)k * (768 * 256);        // rows u, stride 768
    const float* Wo = freq_k_input + (size_t)k * (256 * 256);  // rows d, stride 256

    // ---------------- Phase 1: A_k @ [U_o | W_z] (two accumulator sets) ------
    for (int ku = 0; ku < 256; ku += 16) {
#pragma unroll
        for (int i = 0; i < 2; i++) {
            const int e  = tid + i * 256;          // 0..511
            const int lb = e >> 2;                 // b 0..127
            const int lu = (e & 3) * 4;
            float4 v = *(const float4*)&g_AT[((size_t)lb * 256 + k) * 256 + ku + lu];
            sA[lu + 0][lb] = v.x; sA[lu + 1][lb] = v.y;
            sA[lu + 2][lb] = v.z; sA[lu + 3][lb] = v.w;
        }
        {
            const int wu = tid >> 4;
            const int wc = (tid & 15) * 4;
            *(float4*)&sB1[wu][wc] = *(const float4*)&Uo[(ku + wu) * 768 + v0 + wc];        // U_o
            *(float4*)&sB2[wu][wc] = *(const float4*)&Uo[(ku + wu) * 768 + 512 + v0 + wc];  // W_z
        }
        __syncthreads();
#pragma unroll
        for (int kk = 0; kk < 16; kk++) {
            float a[8], b1[4], b2[4];
#pragma unroll
            for (int i = 0; i < 8; i++) a[i] = sA[kk][rg * 8 + i];
#pragma unroll
            for (int j = 0; j < 4; j++) { b1[j] = sB1[kk][cg * 4 + j]; b2[j] = sB2[kk][cg * 4 + j]; }
#pragma unroll
            for (int i = 0; i < 8; i++)
#pragma unroll
                for (int j = 0; j < 4; j++) {
                    acc_o[i][j] += a[i] * b1[j];
                    acc_z[i][j] += a[i] * b2[j];
                }
        }
        __syncthreads();
    }

    // ---------------- Phase 2: x @ W_o ; Phase 3: z_prev @ V_o ---------------
#pragma unroll
    for (int phase = 0; phase < 2; phase++) {
        const float* L = phase ? z_prev : x_in;
        for (int ku = 0; ku < 256; ku += 16) {
#pragma unroll
            for (int i = 0; i < 2; i++) {
                const int e  = tid + i * 256;
                const int lb = e >> 2;
                const int lu = (e & 3) * 4;
                float4 v = *(const float4*)&L[lb * 256 + ku + lu];
                sA[lu + 0][lb] = v.x; sA[lu + 1][lb] = v.y;
                sA[lu + 2][lb] = v.z; sA[lu + 3][lb] = v.w;
            }
            {
                const int wu = tid >> 4;
                const int wc = (tid & 15) * 4;
                float4 wv;
                if (phase)
                    wv = *(const float4*)&Uo[(ku + wu) * 768 + 256 + v0 + wc];   // V_o
                else
                    wv = *(const float4*)&Wo[(ku + wu) * 256 + v0 + wc];         // W_o
                *(float4*)&sB1[wu][wc] = wv;
            }
            __syncthreads();
#pragma unroll
            for (int kk = 0; kk < 16; kk++) {
                float a[8], b1[4];
#pragma unroll
                for (int i = 0; i < 8; i++) a[i] = sA[kk][rg * 8 + i];
#pragma unroll
                for (int j = 0; j < 4; j++) b1[j] = sB1[kk][cg * 4 + j];
#pragma unroll
                for (int i = 0; i < 8; i++)
#pragma unroll
                    for (int j = 0; j < 4; j++) acc_o[i][j] += a[i] * b1[j];
            }
            __syncthreads();
        }
    }

    // ---------------- Epilogue: activations + k-reduction --------------------
    const float* bo = freq_bias + (size_t)k * 256;
    const float* bz = freq_bias + (size_t)(256 + k) * 256;
#pragma unroll
    for (int i = 0; i < 8; i++) {
        const int b = rg * 8 + i;
#pragma unroll
        for (int j = 0; j < 4; j++) {
            const int v = v0 + cg * 4 + j;
            const float o  = hsig(acc_o[i][j] + bo[v]);
            const float zz = o * tanhf(acc_z[i][j] + bz[v]);
            atomicAdd(&z_out[b * 256 + v], zz);
        }
    }
}

// ============================================================================
// launch
// ============================================================================
extern "C" void kernel_launch(void* const* d_in, const int* in_sizes, int n_in,
                              void* d_out, int out_size)
{
    const float* x        = (const float*)d_in[0];
    const float* t        = (const float*)d_in[1];
    const float* z_prev   = (const float*)d_in[2];
    const float* Im_prev  = (const float*)d_in[3];
    const float* Re_prev  = (const float*)d_in[4];
    const float* omg_prev = (const float*)d_in[5];
    const float* kern     = (const float*)d_in[6];
    const float* recur    = (const float*)d_in[7];
    const float* freq_k   = (const float*)d_in[8];
    const float* freq_ki  = (const float*)d_in[9];
    const float* bias     = (const float*)d_in[10];
    const float* freqb    = (const float*)d_in[11];

    float* out     = (float*)d_out;
    float* z_out   = out;                                  // (B,U)      32768
    float* im_out  = out + 32768;                          // (B,U,U)  8388608
    float* re_out  = out + 32768 + 8388608;                // (B,U,U)  8388608
    float* omg_out = out + 32768 + 2 * 8388608;            // (B,U)      32768

    cudaMemsetAsync(z_out, 0, 32768 * sizeof(float), 0);

    k_gates_gemm<<<dim3(20, 2), 256>>>(x, z_prev, kern, recur, bias);
    k_gates_ew<<<128, 256>>>(omg_prev, t, omg_out);
    k_reim<<<dim3(4, 4, 128), 256>>>(Re_prev, Im_prev, im_out, re_out);
    k_freq<<<dim3(256, 4), 256>>>(x, z_prev, freq_k, freq_ki, freqb, z_out);
}

// round 6
// speedup vs baseline: 2.7253x; 2.7253x over previous
#include <cuda_runtime.h>
#include <cuda_fp16.h>
#include <math.h>
#include <stdint.h>

#define Bq 128
#define Uq 256
#define NG 1280

// ---------------- scratch (static device globals) ----------------------------
__device__ float g_gsum[Bq * NG];
__device__ float g_c  [Bq * Uq];
__device__ float g_fre[Bq * Uq];
__device__ float g_ste[Bq * Uq];
__device__ float g_cos[Bq * Uq];
__device__ float g_sin[Bq * Uq];
__device__ __half g_Ah[(size_t)Uq * Bq * Uq];  // [k][b][u], 16.8MB
__device__ __half g_xh[Bq * Uq];
__device__ __half g_zh[Bq * Uq];

__device__ __forceinline__ float hsig(float v) {
    return fminf(fmaxf(0.2f * v + 0.5f, 0.0f), 1.0f);
}

// ---------------- PTX helpers (sm_80-level only) ------------------------------
__device__ __forceinline__ uint32_t smem_u32(const void* p) {
    uint32_t a;
    asm("{ .reg .u64 t; cvta.to.shared.u64 t, %1; cvt.u32.u64 %0, t; }" : "=r"(a) : "l"(p));
    return a;
}
__device__ __forceinline__ uint32_t packh(float lo, float hi) {
    __half2 h = __floats2half2_rn(lo, hi);   // lo -> low half, hi -> high half
    return *(uint32_t*)&h;
}
__device__ __forceinline__ void sts128(uint32_t a, uint32_t r0, uint32_t r1, uint32_t r2, uint32_t r3) {
    asm volatile("st.shared.v4.b32 [%0], {%1,%2,%3,%4};"
                 :: "r"(a), "r"(r0), "r"(r1), "r"(r2), "r"(r3) : "memory");
}
__device__ __forceinline__ void cpa16(uint32_t dst, const void* src) {
    asm volatile("cp.async.cg.shared.global [%0], [%1], 16;" :: "r"(dst), "l"(src) : "memory");
}
__device__ __forceinline__ void cpa_commit() {
    asm volatile("cp.async.commit_group;" ::: "memory");
}
__device__ __forceinline__ void cpa_wait0() {
    asm volatile("cp.async.wait_group 0;" ::: "memory");
}
__device__ __forceinline__ void ldsm4(uint32_t* r, uint32_t addr) {
    asm volatile("ldmatrix.sync.aligned.m8n8.x4.shared.b16 {%0,%1,%2,%3}, [%4];"
                 : "=r"(r[0]), "=r"(r[1]), "=r"(r[2]), "=r"(r[3]) : "r"(addr));
}
__device__ __forceinline__ void ldsm4t(uint32_t* r, uint32_t addr) {
    asm volatile("ldmatrix.sync.aligned.m8n8.x4.trans.shared.b16 {%0,%1,%2,%3}, [%4];"
                 : "=r"(r[0]), "=r"(r[1]), "=r"(r[2]), "=r"(r[3]) : "r"(addr));
}
__device__ __forceinline__ void mma_f16(float* c, const uint32_t* a, const uint32_t* b) {
    asm volatile(
        "mma.sync.aligned.m16n8k16.row.col.f32.f16.f16.f32 "
        "{%0,%1,%2,%3}, {%4,%5,%6,%7}, {%8,%9}, {%0,%1,%2,%3};"
        : "+f"(c[0]), "+f"(c[1]), "+f"(c[2]), "+f"(c[3])
        : "r"(a[0]), "r"(a[1]), "r"(a[2]), "r"(a[3]), "r"(b[0]), "r"(b[1]));
}

// ============================================================================
// Kernel 1: g_gsum = x @ kernel + z_prev @ recur_k + bias
// ============================================================================
__global__ __launch_bounds__(256) void k_gates_gemm(
    const float* __restrict__ x, const float* __restrict__ z_prev,
    const float* __restrict__ kern, const float* __restrict__ recur,
    const float* __restrict__ bias)
{
    __shared__ float sX[16][68];
    __shared__ float sW[16][64];
    const int tid = threadIdx.x;
    const int j0 = blockIdx.x * 64, b0 = blockIdx.y * 64;
    const int rg = tid >> 4, cg = tid & 15;
    float acc[4][4];
#pragma unroll
    for (int i = 0; i < 4; i++)
#pragma unroll
        for (int j = 0; j < 4; j++) acc[i][j] = 0.f;
#pragma unroll
    for (int pass = 0; pass < 2; pass++) {
        const float* L = pass ? z_prev : x;
        const float* W = pass ? recur : kern;
        for (int d0 = 0; d0 < 256; d0 += 16) {
            {
                const int lb = tid >> 2, lu = (tid & 3) * 4;
                float4 v = *(const float4*)&L[(b0 + lb) * 256 + d0 + lu];
                sX[lu][lb] = v.x; sX[lu + 1][lb] = v.y; sX[lu + 2][lb] = v.z; sX[lu + 3][lb] = v.w;
            }
            {
                const int wu = tid >> 4, wc = (tid & 15) * 4;
                *(float4*)&sW[wu][wc] = *(const float4*)&W[(d0 + wu) * NG + j0 + wc];
            }
            __syncthreads();
#pragma unroll
            for (int kk = 0; kk < 16; kk++) {
                float a[4], bb[4];
#pragma unroll
                for (int i = 0; i < 4; i++) a[i] = sX[kk][rg * 4 + i];
#pragma unroll
                for (int j = 0; j < 4; j++) bb[j] = sW[kk][cg * 4 + j];
#pragma unroll
                for (int i = 0; i < 4; i++)
#pragma unroll
                    for (int j = 0; j < 4; j++) acc[i][j] += a[i] * bb[j];
            }
            __syncthreads();
        }
    }
#pragma unroll
    for (int i = 0; i < 4; i++) {
        const int b = b0 + rg * 4 + i;
#pragma unroll
        for (int j = 0; j < 4; j++) {
            const int jj = j0 + cg * 4 + j;
            g_gsum[b * NG + jj] = acc[i][j] + bias[jj];
        }
    }
}

// ============================================================================
// Kernel 2: elementwise gates + omega out + cos/sin + fp16 copies of x, z_prev
// ============================================================================
__global__ __launch_bounds__(256) void k_gates_ew(
    const float* __restrict__ x, const float* __restrict__ z_prev,
    const float* __restrict__ omg_prev, const float* __restrict__ t,
    float* __restrict__ out_omg)
{
    const int idx = blockIdx.x * blockDim.x + threadIdx.x;
    const int b = idx >> 8, u = idx & 255;
    const float* g = &g_gsum[b * NG];
    const float i_g = hsig(g[u]);
    const float fre = hsig(g[Uq + u]);
    const float ste = hsig(g[2 * Uq + u]);
    const float gg  = tanhf(g[3 * Uq + u]);
    g_c[idx] = i_g * gg; g_fre[idx] = fre; g_ste[idx] = ste;
    const float th = omg_prev[idx] * t[b];
    g_cos[idx] = cosf(th); g_sin[idx] = sinf(th);
    out_omg[idx] = g[4 * Uq + u];
    g_xh[idx] = __float2half_rn(x[idx]);
    g_zh[idx] = __float2half_rn(z_prev[idx]);
}

// ============================================================================
// Kernel 3: Re/Im update + A = sqrt(Re^2+Im^2) written as fp16 [k][b][u]
// ============================================================================
__global__ __launch_bounds__(256) void k_reim(
    const float* __restrict__ Re_prev, const float* __restrict__ Im_prev,
    float* __restrict__ Im_out, float* __restrict__ Re_out)
{
    __shared__ float sA[64][65];
    const int b = blockIdx.z, i0 = blockIdx.y * 64, j0 = blockIdx.x * 64;
    const int tj = threadIdx.x & 63, ti = threadIdx.x >> 6;
    const float fre_j = g_fre[b * Uq + j0 + tj];
    const float cosj = g_cos[b * Uq + j0 + tj];
    const float sinj = g_sin[b * Uq + j0 + tj];
#pragma unroll
    for (int r = 0; r < 16; r++) {
        const int i = ti + r * 4;
        const float ste_i = g_ste[b * Uq + i0 + i];
        const float ci = g_c[b * Uq + i0 + i];
        const size_t idx = ((size_t)b * Uq + (i0 + i)) * Uq + j0 + tj;
        const float f = ste_i * fre_j;
        const float re = f * Re_prev[idx] + ci * cosj;
        const float im = f * Im_prev[idx] + ci * sinj;
        Re_out[idx] = re; Im_out[idx] = im;
        sA[i][tj] = sqrtf(re * re + im * im);
    }
    __syncthreads();
    // g_Ah[k][b][u] = A[b][u][k];  value A[b][i0+tj][j0+j] = sA[tj][j]
#pragma unroll
    for (int r = 0; r < 16; r++) {
        const int j = ti + r * 4;
        g_Ah[((size_t)(j0 + j) * 128 + b) * 256 + i0 + tj] = __float2half_rn(sA[tj][j]);
    }
}

// ============================================================================
// Kernel 4: per-k fused GEMMs via mma.sync fp16.
// Grid (256 k, 2 vhalf). 256 threads, warps 4(M)x2(N), warp tile 32x64.
// Phases (4 chunks of K=64 each): 0: A@Uo  1: x@Wo  2: z@Vo  -> C_o (to smem)
//                                 3: A@Wz -> C_z. Epilogue: hsig*tanh + atomics.
// ============================================================================
#define LDA 144           // 128B fp16 row + 16B pad
#define LDB 272           // 256B fp16 row + 16B pad
#define STG (128*LDA + 64*LDB)   // 35840
#define OFF_CO (2*STG)           // 71680
#define SMEM_TOT (OFF_CO + 256*65*4)  // 138240

__global__ __launch_bounds__(256, 1) void k_freq_mma(
    const float* __restrict__ freq_k, const float* __restrict__ freq_ki,
    const float* __restrict__ freqb, float* __restrict__ z_out)
{
    extern __shared__ char smem[];
    const uint32_t sbase = smem_u32(smem);
    const int tid = threadIdx.x, l = tid & 31, w = tid >> 5;
    const int wm = w & 3, wn = w >> 2;
    const int k = blockIdx.x, vh = blockIdx.y;

    float acc[2][8][4];
#pragma unroll
    for (int i = 0; i < 64; i++) ((float*)acc)[i] = 0.f;

    const uint32_t a_base = (uint32_t)((wm * 32 + (l & 15)) * LDA + (l >> 4) * 16);
    const uint32_t b_base = (uint32_t)((l & 15) * LDB + wn * 128 + (l >> 4) * 16);

    auto lhs_of = [&](int c) -> const __half* {
        const int p = c >> 2, kc = (c & 3) * 64;
        if (p == 1) return g_xh + kc;
        if (p == 2) return g_zh + kc;
        return g_Ah + (size_t)k * 32768 + kc;
    };
    auto bsrc_of = [&](int c, int& stride) -> const float* {
        const int p = c >> 2, kc = (c & 3) * 64;
        if (p == 1) { stride = 256; return freq_ki + (size_t)k * 65536 + (size_t)kc * 256 + vh * 128; }
        stride = 768;
        const int off = (p == 0) ? 0 : (p == 2) ? 256 : 512;
        return freq_k + (size_t)k * 196608 + (size_t)kc * 768 + off + vh * 128;
    };

    float4 hb[4][2];

    // ---- prologue: cp.async LHS(0) -> buf0; LDG B(0) -> regs ----------------
    {
        const __half* ls = lhs_of(0);
#pragma unroll
        for (int i = 0; i < 4; i++) {
            const int idx = tid + i * 256;
            const int row = idx >> 3, g = idx & 7;
            cpa16(sbase + row * LDA + g * 16, ls + row * 256 + g * 8);
        }
        cpa_commit();
        int bstr; const float* bs = bsrc_of(0, bstr);
#pragma unroll
        for (int i = 0; i < 4; i++) {
            const int idx = tid + i * 256;
            const int r = idx >> 4, g = idx & 15;
            hb[i][0] = __ldg((const float4*)(bs + (size_t)r * bstr + g * 8));
            hb[i][1] = __ldg((const float4*)(bs + (size_t)r * bstr + g * 8 + 4));
        }
    }

#pragma unroll 1
    for (int c = 0; c < 16; c++) {
        const int buf = c & 1;
        const uint32_t sA = sbase + buf * STG;
        const uint32_t sB = sA + 128 * LDA;

        // store B(c) regs -> smem (convert fp32 -> fp16)
#pragma unroll
        for (int i = 0; i < 4; i++) {
            const int idx = tid + i * 256;
            const int r = idx >> 4, g = idx & 15;
            const uint32_t p0 = packh(hb[i][0].x, hb[i][0].y);
            const uint32_t p1 = packh(hb[i][0].z, hb[i][0].w);
            const uint32_t p2 = packh(hb[i][1].x, hb[i][1].y);
            const uint32_t p3 = packh(hb[i][1].z, hb[i][1].w);
            sts128(sB + r * LDB + g * 16, p0, p1, p2, p3);
        }
        cpa_wait0();
        __syncthreads();

        if (c < 15) {
            const __half* ls = lhs_of(c + 1);
            const uint32_t sA2 = sbase + (buf ^ 1) * STG;
#pragma unroll
            for (int i = 0; i < 4; i++) {
                const int idx = tid + i * 256;
                const int row = idx >> 3, g = idx & 7;
                cpa16(sA2 + row * LDA + g * 16, ls + row * 256 + g * 8);
            }
            cpa_commit();
            int bstr; const float* bs = bsrc_of(c + 1, bstr);
#pragma unroll
            for (int i = 0; i < 4; i++) {
                const int idx = tid + i * 256;
                const int r = idx >> 4, g = idx & 15;
                hb[i][0] = __ldg((const float4*)(bs + (size_t)r * bstr + g * 8));
                hb[i][1] = __ldg((const float4*)(bs + (size_t)r * bstr + g * 8 + 4));
            }
        }

        // MMA over chunk c: 4 k16 steps
#pragma unroll
        for (int s = 0; s < 4; s++) {
            uint32_t af[2][4], bfr[4][4];
            ldsm4(af[0], sA + a_base + s * 32);
            ldsm4(af[1], sA + a_base + 16 * LDA + s * 32);
#pragma unroll
            for (int nt = 0; nt < 4; nt++)
                ldsm4t(bfr[nt], sB + b_base + s * 16 * LDB + nt * 32);
#pragma unroll
            for (int mt = 0; mt < 2; mt++)
#pragma unroll
                for (int nt = 0; nt < 4; nt++) {
                    mma_f16(acc[mt][2 * nt],     af[mt], &bfr[nt][0]);
                    mma_f16(acc[mt][2 * nt + 1], af[mt], &bfr[nt][2]);
                }
        }

        if (c == 11) {
            // C_o complete: stash in private smem, reset acc for C_z
            float* sCo = (float*)(smem + OFF_CO);
#pragma unroll
            for (int i = 0; i < 64; i++) {
                sCo[tid * 65 + i] = ((float*)acc)[i];
                ((float*)acc)[i] = 0.f;
            }
        }
    }

    // ---- epilogue: zz = hsig(C_o + b_o) * tanh(C_z + b_z); z += zz ----------
    const float* sCo = (const float*)(smem + OFF_CO);
    const float* bo = freqb + (size_t)k * 256;
    const float* bz = freqb + (size_t)(256 + k) * 256;
#pragma unroll
    for (int mt = 0; mt < 2; mt++)
#pragma unroll
        for (int j = 0; j < 8; j++)
#pragma unroll
            for (int r = 0; r < 4; r++) {
                const int b = wm * 32 + mt * 16 + (l >> 2) + (r >> 1) * 8;
                const int v = vh * 128 + wn * 64 + j * 8 + (l & 3) * 2 + (r & 1);
                const float co = sCo[tid * 65 + mt * 32 + j * 4 + r];
                const float o = hsig(co + __ldg(bo + v));
                const float zz = o * tanhf(acc[mt][j][r] + __ldg(bz + v));
                atomicAdd(&z_out[b * 256 + v], zz);
            }
}

// ============================================================================
// launch
// ============================================================================
extern "C" void kernel_launch(void* const* d_in, const int* in_sizes, int n_in,
                              void* d_out, int out_size)
{
    const float* x        = (const float*)d_in[0];
    const float* t        = (const float*)d_in[1];
    const float* z_prev   = (const float*)d_in[2];
    const float* Im_prev  = (const float*)d_in[3];
    const float* Re_prev  = (const float*)d_in[4];
    const float* omg_prev = (const float*)d_in[5];
    const float* kern     = (const float*)d_in[6];
    const float* recur    = (const float*)d_in[7];
    const float* freq_k   = (const float*)d_in[8];
    const float* freq_ki  = (const float*)d_in[9];
    const float* bias     = (const float*)d_in[10];
    const float* freqb    = (const float*)d_in[11];

    float* out     = (float*)d_out;
    float* z_out   = out;
    float* im_out  = out + 32768;
    float* re_out  = out + 32768 + 8388608;
    float* omg_out = out + 32768 + 2 * 8388608;

    static int smem_set = 0;
    if (!smem_set) {
        cudaFuncSetAttribute(k_freq_mma, cudaFuncAttributeMaxDynamicSharedMemorySize, SMEM_TOT);
        smem_set = 1;
    }

    cudaMemsetAsync(z_out, 0, 32768 * sizeof(float), 0);
    k_gates_gemm<<<dim3(20, 2), 256>>>(x, z_prev, kern, recur, bias);
    k_gates_ew<<<128, 256>>>(x, z_prev, omg_prev, t, omg_out);
    k_reim<<<dim3(4, 4, 128), 256>>>(Re_prev, Im_prev, im_out, re_out);
    k_freq_mma<<<dim3(256, 2), 256, SMEM_TOT>>>(freq_k, freq_ki, freqb, z_out);
}

// round 7
// speedup vs baseline: 2.9469x; 1.0813x over previous
#include <cuda_runtime.h>
#include <cuda_fp16.h>
#include <math.h>
#include <stdint.h>

#define Bq 128
#define Uq 256
#define NG 1280

// ---------------- scratch (static device globals) ----------------------------
__device__ float g_gsum[Bq * NG];
__device__ float g_c  [Bq * Uq];
__device__ float g_fre[Bq * Uq];
__device__ float g_ste[Bq * Uq];
__device__ float g_cos[Bq * Uq];
__device__ float g_sin[Bq * Uq];
__device__ __half g_Ah[(size_t)Uq * Bq * Uq];  // [k][b][u], 16.8MB
__device__ __half g_xh[Bq * Uq];
__device__ __half g_zh[Bq * Uq];

__device__ __forceinline__ float hsig(float v) {
    return fminf(fmaxf(0.2f * v + 0.5f, 0.0f), 1.0f);
}

// ---------------- PTX helpers (sm_80-level only) ------------------------------
__device__ __forceinline__ uint32_t smem_u32(const void* p) {
    uint32_t a;
    asm("{ .reg .u64 t; cvta.to.shared.u64 t, %1; cvt.u32.u64 %0, t; }" : "=r"(a) : "l"(p));
    return a;
}
__device__ __forceinline__ uint32_t packh(float lo, float hi) {
    __half2 h = __floats2half2_rn(lo, hi);
    return *(uint32_t*)&h;
}
__device__ __forceinline__ void sts128(uint32_t a, uint32_t r0, uint32_t r1, uint32_t r2, uint32_t r3) {
    asm volatile("st.shared.v4.b32 [%0], {%1,%2,%3,%4};"
                 :: "r"(a), "r"(r0), "r"(r1), "r"(r2), "r"(r3) : "memory");
}
__device__ __forceinline__ void cpa16(uint32_t dst, const void* src) {
    asm volatile("cp.async.cg.shared.global [%0], [%1], 16;" :: "r"(dst), "l"(src) : "memory");
}
__device__ __forceinline__ void cpa_commit() {
    asm volatile("cp.async.commit_group;" ::: "memory");
}
__device__ __forceinline__ void cpa_wait0() {
    asm volatile("cp.async.wait_group 0;" ::: "memory");
}
__device__ __forceinline__ void ldsm4(uint32_t* r, uint32_t addr) {
    asm volatile("ldmatrix.sync.aligned.m8n8.x4.shared.b16 {%0,%1,%2,%3}, [%4];"
                 : "=r"(r[0]), "=r"(r[1]), "=r"(r[2]), "=r"(r[3]) : "r"(addr));
}
__device__ __forceinline__ void ldsm4t(uint32_t* r, uint32_t addr) {
    asm volatile("ldmatrix.sync.aligned.m8n8.x4.trans.shared.b16 {%0,%1,%2,%3}, [%4];"
                 : "=r"(r[0]), "=r"(r[1]), "=r"(r[2]), "=r"(r[3]) : "r"(addr));
}
__device__ __forceinline__ void mma_f16(float* c, const uint32_t* a, const uint32_t* b) {
    asm volatile(
        "mma.sync.aligned.m16n8k16.row.col.f32.f16.f16.f32 "
        "{%0,%1,%2,%3}, {%4,%5,%6,%7}, {%8,%9}, {%0,%1,%2,%3};"
        : "+f"(c[0]), "+f"(c[1]), "+f"(c[2]), "+f"(c[3])
        : "r"(a[0]), "r"(a[1]), "r"(a[2]), "r"(a[3]), "r"(b[0]), "r"(b[1]));
}

// ============================================================================
// Kernel 1: g_gsum = x @ kernel + z_prev @ recur_k + bias
// ============================================================================
__global__ __launch_bounds__(256) void k_gates_gemm(
    const float* __restrict__ x, const float* __restrict__ z_prev,
    const float* __restrict__ kern, const float* __restrict__ recur,
    const float* __restrict__ bias)
{
    __shared__ float sX[16][68];
    __shared__ float sW[16][64];
    const int tid = threadIdx.x;
    const int j0 = blockIdx.x * 64, b0 = blockIdx.y * 64;
    const int rg = tid >> 4, cg = tid & 15;
    float acc[4][4];
#pragma unroll
    for (int i = 0; i < 4; i++)
#pragma unroll
        for (int j = 0; j < 4; j++) acc[i][j] = 0.f;
#pragma unroll
    for (int pass = 0; pass < 2; pass++) {
        const float* L = pass ? z_prev : x;
        const float* W = pass ? recur : kern;
        for (int d0 = 0; d0 < 256; d0 += 16) {
            {
                const int lb = tid >> 2, lu = (tid & 3) * 4;
                float4 v = *(const float4*)&L[(b0 + lb) * 256 + d0 + lu];
                sX[lu][lb] = v.x; sX[lu + 1][lb] = v.y; sX[lu + 2][lb] = v.z; sX[lu + 3][lb] = v.w;
            }
            {
                const int wu = tid >> 4, wc = (tid & 15) * 4;
                *(float4*)&sW[wu][wc] = *(const float4*)&W[(d0 + wu) * NG + j0 + wc];
            }
            __syncthreads();
#pragma unroll
            for (int kk = 0; kk < 16; kk++) {
                float a[4], bb[4];
#pragma unroll
                for (int i = 0; i < 4; i++) a[i] = sX[kk][rg * 4 + i];
#pragma unroll
                for (int j = 0; j < 4; j++) bb[j] = sW[kk][cg * 4 + j];
#pragma unroll
                for (int i = 0; i < 4; i++)
#pragma unroll
                    for (int j = 0; j < 4; j++) acc[i][j] += a[i] * bb[j];
            }
            __syncthreads();
        }
    }
#pragma unroll
    for (int i = 0; i < 4; i++) {
        const int b = b0 + rg * 4 + i;
#pragma unroll
        for (int j = 0; j < 4; j++) {
            const int jj = j0 + cg * 4 + j;
            g_gsum[b * NG + jj] = acc[i][j] + bias[jj];
        }
    }
}

// ============================================================================
// Kernel 2: elementwise gates + omega out + cos/sin + fp16 copies of x, z_prev
// ============================================================================
__global__ __launch_bounds__(256) void k_gates_ew(
    const float* __restrict__ x, const float* __restrict__ z_prev,
    const float* __restrict__ omg_prev, const float* __restrict__ t,
    float* __restrict__ out_omg)
{
    const int idx = blockIdx.x * blockDim.x + threadIdx.x;
    const int b = idx >> 8, u = idx & 255;
    const float* g = &g_gsum[b * NG];
    const float i_g = hsig(g[u]);
    const float fre = hsig(g[Uq + u]);
    const float ste = hsig(g[2 * Uq + u]);
    const float gg  = tanhf(g[3 * Uq + u]);
    g_c[idx] = i_g * gg; g_fre[idx] = fre; g_ste[idx] = ste;
    const float th = omg_prev[idx] * t[b];
    g_cos[idx] = cosf(th); g_sin[idx] = sinf(th);
    out_omg[idx] = g[4 * Uq + u];
    g_xh[idx] = __float2half_rn(x[idx]);
    g_zh[idx] = __float2half_rn(z_prev[idx]);
}

// ============================================================================
// Kernel 3: Re/Im update + A = sqrt(Re^2+Im^2) written as fp16 [k][b][u]
// ============================================================================
__global__ __launch_bounds__(256) void k_reim(
    const float* __restrict__ Re_prev, const float* __restrict__ Im_prev,
    float* __restrict__ Im_out, float* __restrict__ Re_out)
{
    __shared__ float sA[64][65];
    const int b = blockIdx.z, i0 = blockIdx.y * 64, j0 = blockIdx.x * 64;
    const int tj = threadIdx.x & 63, ti = threadIdx.x >> 6;
    const float fre_j = g_fre[b * Uq + j0 + tj];
    const float cosj = g_cos[b * Uq + j0 + tj];
    const float sinj = g_sin[b * Uq + j0 + tj];
#pragma unroll
    for (int r = 0; r < 16; r++) {
        const int i = ti + r * 4;
        const float ste_i = g_ste[b * Uq + i0 + i];
        const float ci = g_c[b * Uq + i0 + i];
        const size_t idx = ((size_t)b * Uq + (i0 + i)) * Uq + j0 + tj;
        const float f = ste_i * fre_j;
        const float re = f * Re_prev[idx] + ci * cosj;
        const float im = f * Im_prev[idx] + ci * sinj;
        Re_out[idx] = re; Im_out[idx] = im;
        sA[i][tj] = sqrtf(re * re + im * im);
    }
    __syncthreads();
#pragma unroll
    for (int r = 0; r < 16; r++) {
        const int j = ti + r * 4;
        g_Ah[((size_t)(j0 + j) * 128 + b) * 256 + i0 + tj] = __float2half_rn(sA[tj][j]);
    }
}

// ============================================================================
// Kernel 4: per-k fused GEMMs via mma.sync fp16, v2.
// Grid (256 k, 4 vq). 256 threads, warps 4(M)x2(N), warp tile 32x32.
// Block tile 128(b) x 64(v). Both C_o and C_z live in registers.
// Chunks of K=64:  c 0-3:  A @ [U_o | W_z]  -> acc_o, acc_z  (A read once)
//                  c 4-7:  x @ W_o          -> acc_o
//                  c 8-11: z_prev @ V_o     -> acc_o
// Epilogue: z[b,v] += hsig(acc_o+b_o) * tanh(acc_z+b_z) via atomics.
// ============================================================================
#define LDA 144                 // 64 fp16 (128B) + 16B pad
#define LDB 144
#define A_BYTES (128*LDA)       // 18432
#define B_BYTES (64*LDB)        // 9216
#define STG (A_BYTES + 2*B_BYTES)   // 36864
#define SMEM_TOT (2*STG)            // 73728

__global__ __launch_bounds__(256, 2) void k_freq_mma(
    const float* __restrict__ freq_k, const float* __restrict__ freq_ki,
    const float* __restrict__ freqb, float* __restrict__ z_out)
{
    extern __shared__ char smem[];
    const uint32_t sbase = smem_u32(smem);
    const int tid = threadIdx.x, l = tid & 31, w = tid >> 5;
    const int wm = w & 3, wn = w >> 2;
    const int k = blockIdx.x, v0 = blockIdx.y * 64;

    float acc_o[2][4][4], acc_z[2][4][4];
#pragma unroll
    for (int i = 0; i < 32; i++) { ((float*)acc_o)[i] = 0.f; ((float*)acc_z)[i] = 0.f; }

    const uint32_t a_base = (uint32_t)((wm * 32 + (l & 15)) * LDA + (l >> 4) * 16);
    const uint32_t b_base = (uint32_t)((l & 15) * LDB + wn * 64 + (l >> 4) * 16);

    // LHS (fp16, row-major [128 x 256], take k-chunk c*64)
    auto lhs_of = [&](int c) -> const __half* {
        if (c < 4)  return g_Ah + (size_t)k * 32768 + c * 64;
        if (c < 8)  return g_xh + (c - 4) * 64;
        return g_zh + (c - 8) * 64;
    };
    // primary B tile (64k x 64v fp32 slab)
    auto b0_of = [&](int c, int& stride) -> const float* {
        if (c < 4)  { stride = 768; return freq_k  + (size_t)k * 196608 + (size_t)c * 64 * 768 + v0; }
        if (c < 8)  { stride = 256; return freq_ki + (size_t)k * 65536  + (size_t)(c - 4) * 64 * 256 + v0; }
        stride = 768; return freq_k + (size_t)k * 196608 + (size_t)(c - 8) * 64 * 768 + 256 + v0;
    };

    float4 hb[8];

    auto load_lhs = [&](int c, int buf) {
        const __half* ls = lhs_of(c);
        const uint32_t dst = sbase + buf * STG;
#pragma unroll
        for (int i = 0; i < 4; i++) {
            const int idx = tid + i * 256;
            const int row = idx >> 3, g = idx & 7;
            cpa16(dst + row * LDA + g * 16, ls + row * 256 + g * 8);
        }
        cpa_commit();
    };
    auto load_b_regs = [&](int c) {
        int st; const float* b0 = b0_of(c, st);
#pragma unroll
        for (int i = 0; i < 2; i++) {
            const int idx = tid + i * 256;
            const int r = idx >> 3, g = idx & 7;
            hb[2 * i]     = __ldg((const float4*)(b0 + (size_t)r * st + g * 8));
            hb[2 * i + 1] = __ldg((const float4*)(b0 + (size_t)r * st + g * 8 + 4));
        }
        if (c < 4) {
            const float* b1 = freq_k + (size_t)k * 196608 + (size_t)c * 64 * 768 + 512 + v0;
#pragma unroll
            for (int i = 0; i < 2; i++) {
                const int idx = tid + i * 256;
                const int r = idx >> 3, g = idx & 7;
                hb[4 + 2 * i]     = __ldg((const float4*)(b1 + (size_t)r * 768 + g * 8));
                hb[4 + 2 * i + 1] = __ldg((const float4*)(b1 + (size_t)r * 768 + g * 8 + 4));
            }
        }
    };
    auto store_b = [&](int c, int buf) {
        const uint32_t sB0 = sbase + buf * STG + A_BYTES;
#pragma unroll
        for (int i = 0; i < 2; i++) {
            const int idx = tid + i * 256;
            const int r = idx >> 3, g = idx & 7;
            sts128(sB0 + r * LDB + g * 16,
                   packh(hb[2 * i].x, hb[2 * i].y), packh(hb[2 * i].z, hb[2 * i].w),
                   packh(hb[2 * i + 1].x, hb[2 * i + 1].y), packh(hb[2 * i + 1].z, hb[2 * i + 1].w));
        }
        if (c < 4) {
            const uint32_t sB1 = sB0 + B_BYTES;
#pragma unroll
            for (int i = 0; i < 2; i++) {
                const int idx = tid + i * 256;
                const int r = idx >> 3, g = idx & 7;
                sts128(sB1 + r * LDB + g * 16,
                       packh(hb[4 + 2 * i].x, hb[4 + 2 * i].y), packh(hb[4 + 2 * i].z, hb[4 + 2 * i].w),
                       packh(hb[5 + 2 * i].x, hb[5 + 2 * i].y), packh(hb[5 + 2 * i].z, hb[5 + 2 * i].w));
            }
        }
    };

    // ---- prologue ----------------------------------------------------------
    load_lhs(0, 0);
    load_b_regs(0);

#pragma unroll 1
    for (int c = 0; c < 12; c++) {
        const int buf = c & 1;
        store_b(c, buf);
        cpa_wait0();
        __syncthreads();

        if (c < 11) {
            load_lhs(c + 1, buf ^ 1);
            load_b_regs(c + 1);
        }

        const uint32_t sA  = sbase + buf * STG;
        const uint32_t sB0 = sA + A_BYTES;
        const uint32_t sB1 = sB0 + B_BYTES;

#pragma unroll
        for (int s = 0; s < 4; s++) {
            uint32_t af[2][4], bf[2][4];
            ldsm4(af[0], sA + a_base + s * 32);
            ldsm4(af[1], sA + a_base + 16 * LDA + s * 32);
#pragma unroll
            for (int nt = 0; nt < 2; nt++)
                ldsm4t(bf[nt], sB0 + b_base + s * 16 * LDB + nt * 32);
#pragma unroll
            for (int mt = 0; mt < 2; mt++)
#pragma unroll
                for (int nt = 0; nt < 2; nt++) {
                    mma_f16(acc_o[mt][2 * nt],     af[mt], &bf[nt][0]);
                    mma_f16(acc_o[mt][2 * nt + 1], af[mt], &bf[nt][2]);
                }
            if (c < 4) {
                uint32_t bz[2][4];
#pragma unroll
                for (int nt = 0; nt < 2; nt++)
                    ldsm4t(bz[nt], sB1 + b_base + s * 16 * LDB + nt * 32);
#pragma unroll
                for (int mt = 0; mt < 2; mt++)
#pragma unroll
                    for (int nt = 0; nt < 2; nt++) {
                        mma_f16(acc_z[mt][2 * nt],     af[mt], &bz[nt][0]);
                        mma_f16(acc_z[mt][2 * nt + 1], af[mt], &bz[nt][2]);
                    }
            }
        }
    }

    // ---- epilogue: zz = hsig(C_o + b_o) * tanh(C_z + b_z); z += zz ----------
    const float* bo = freqb + (size_t)k * 256;
    const float* bz = freqb + (size_t)(256 + k) * 256;
#pragma unroll
    for (int mt = 0; mt < 2; mt++)
#pragma unroll
        for (int j = 0; j < 4; j++)
#pragma unroll
            for (int r = 0; r < 4; r++) {
                const int b = wm * 32 + mt * 16 + (l >> 2) + (r >> 1) * 8;
                const int v = v0 + wn * 32 + j * 8 + (l & 3) * 2 + (r & 1);
                const float o = hsig(acc_o[mt][j][r] + __ldg(bo + v));
                const float zz = o * tanhf(acc_z[mt][j][r] + __ldg(bz + v));
                atomicAdd(&z_out[b * 256 + v], zz);
            }
}

// ============================================================================
// launch
// ============================================================================
extern "C" void kernel_launch(void* const* d_in, const int* in_sizes, int n_in,
                              void* d_out, int out_size)
{
    const float* x        = (const float*)d_in[0];
    const float* t        = (const float*)d_in[1];
    const float* z_prev   = (const float*)d_in[2];
    const float* Im_prev  = (const float*)d_in[3];
    const float* Re_prev  = (const float*)d_in[4];
    const float* omg_prev = (const float*)d_in[5];
    const float* kern     = (const float*)d_in[6];
    const float* recur    = (const float*)d_in[7];
    const float* freq_k   = (const float*)d_in[8];
    const float* freq_ki  = (const float*)d_in[9];
    const float* bias     = (const float*)d_in[10];
    const float* freqb    = (const float*)d_in[11];

    float* out     = (float*)d_out;
    float* z_out   = out;
    float* im_out  = out + 32768;
    float* re_out  = out + 32768 + 8388608;
    float* omg_out = out + 32768 + 2 * 8388608;

    static int smem_set = 0;
    if (!smem_set) {
        cudaFuncSetAttribute(k_freq_mma, cudaFuncAttributeMaxDynamicSharedMemorySize, SMEM_TOT);
        smem_set = 1;
    }

    cudaMemsetAsync(z_out, 0, 32768 * sizeof(float), 0);
    k_gates_gemm<<<dim3(20, 2), 256>>>(x, z_prev, kern, recur, bias);
    k_gates_ew<<<128, 256>>>(x, z_prev, omg_prev, t, omg_out);
    k_reim<<<dim3(4, 4, 128), 256>>>(Re_prev, Im_prev, im_out, re_out);
    k_freq_mma<<<dim3(256, 4), 256, SMEM_TOT>>>(freq_k, freq_ki, freqb, z_out);
}